// round 4
// baseline (speedup 1.0000x reference)
#include <cuda_runtime.h>

// PureCascadedBitFFN: out[elem, j] = j-th bit (LSB=0) of
// k = ceil(distance[elem] - 0.5) (exact reduction of the sigmoid cascade).
//
// 128 MB f32 output: pure HBM-write-bound. Store mapping unchanged from the
// 23.0us kernel (block tile = 2048 quads, 256 threads x 8 coalesced 512B
// STG.128 bursts, __stcs evict-first). This round removes the 4x-redundant
// global read stream: each distance is loaded ONCE (coalesced float2),
// converted to int ONCE, and broadcast through 2KB of smem.
//
// Shapes fixed: 512*4096 elems -> 8,388,608 quads = 4096 blocks * 2048.

__global__ __launch_bounds__(256) void cascaded_bits_kernel(
    const float* __restrict__ dist,
    float4* __restrict__ out)
{
    __shared__ int sk[512];               // k per element in this block tile

    const int tid  = threadIdx.x;
    const int base = blockIdx.x * 2048;   // first quad of this block

    // Phase 1: 256 threads load the tile's 512 unique distances (float2 each),
    // convert once, stash in smem.
    {
        float2 d2 = ((const float2*)dist)[(base >> 3) + tid];
        // k = ceil(r - 0.5): exact round-half-down for r in [0, 65535)
        sk[2 * tid + 0] = __float2int_ru(d2.x - 0.5f);
        sk[2 * tid + 1] = __float2int_ru(d2.y - 0.5f);
    }
    __syncthreads();

    // Phase 2: 8 coalesced 512B store bursts per warp, k from smem broadcast.
    #pragma unroll
    for (int i = 0; i < 8; i++) {
        const int lq  = tid + i * 256;    // local quad index in [0, 2048)
        const int k   = sk[lq >> 2];      // 4-lane smem broadcast
        const int bit = (lq & 3) << 2;    // starting bit: 0,4,8,12
        float4 v;
        v.x = (float)((k >> (bit + 0)) & 1);
        v.y = (float)((k >> (bit + 1)) & 1);
        v.z = (float)((k >> (bit + 2)) & 1);
        v.w = (float)((k >> (bit + 3)) & 1);
        __stcs(&out[base + lq], v);       // streaming store: evict-first in L2
    }
}

extern "C" void kernel_launch(void* const* d_in, const int* in_sizes, int n_in,
                              void* d_out, int out_size)
{
    const float* dist = (const float*)d_in[0];
    float4* out = (float4*)d_out;

    int n_elems = in_sizes[0];            // 512*4096 = 2,097,152
    int nquads  = n_elems * 4;            // 8,388,608
    int blocks  = nquads / 2048;          // 4096 (exact)

    cascaded_bits_kernel<<<blocks, 256>>>(dist, out);
}